// round 1
// baseline (speedup 1.0000x reference)
#include <cuda_runtime.h>
#include <math.h>

#define NN 50000
#define NE 800000
#define HD 64
#define NLAYERS 4
#define EK 193          // 2H + 1 + H
#define SA_STRIDE 196
#define SM_STRIDE 68

#define EDGE_SMEM (39168 * 4)
#define NODE_SMEM (25216 * 4)

// persistent scratch (no runtime allocation allowed)
__device__ float g_h[NN * HD];
__device__ float g_e[NE * HD];
__device__ float g_x[NN * 3];
__device__ float g_dx[NN * 3];    // zero-initialized; kernels restore to zero after use
__device__ float g_agg[NN * HD];  // zero-initialized; kernels restore to zero after use

__device__ __forceinline__ float silu_f(float v) {
    return v / (1.0f + __expf(-v));
}

// ---------------------------------------------------------------- embeddings
__global__ void k_node_embed(const float* __restrict__ h,
                             const float* __restrict__ W,
                             const float* __restrict__ b) {
    __shared__ float sW[16 * 64];
    __shared__ float sb[64];
    int tid = threadIdx.x;
    for (int i = tid; i < 16 * 64; i += blockDim.x) sW[i] = W[i];
    if (tid < 64) sb[tid] = b[tid];
    __syncthreads();
    int gid = blockIdx.x * blockDim.x + tid;
    if (gid >= NN * HD) return;
    int n = gid >> 6, j = gid & 63;
    float acc = sb[j];
#pragma unroll
    for (int k = 0; k < 16; k++) acc += h[n * 16 + k] * sW[k * 64 + j];
    g_h[gid] = acc;
}

__global__ void k_edge_embed(const float* __restrict__ ea,
                             const float* __restrict__ W,
                             const float* __restrict__ b) {
    __shared__ float sW[8 * 64];
    __shared__ float sb[64];
    int tid = threadIdx.x;
    for (int i = tid; i < 8 * 64; i += blockDim.x) sW[i] = W[i];
    if (tid < 64) sb[tid] = b[tid];
    __syncthreads();
    int gid = blockIdx.x * blockDim.x + tid;
    if (gid >= NE * HD) return;
    int e = gid >> 6, j = gid & 63;
    float acc = sb[j];
#pragma unroll
    for (int k = 0; k < 8; k++) acc += ea[e * 8 + k] * sW[k * 64 + j];
    g_e[gid] = acc;
}

__global__ void k_xinit(const float* __restrict__ x) {
    int i = blockIdx.x * blockDim.x + threadIdx.x;
    if (i < NN * 3) g_x[i] = x[i];
}

// ---------------------------------------------------------------- edge layer
// One block = 64 edges. Fused: gather -> silu(A@W1+b1) -> silu(.@W2+b2)*mask
//  -> store e / scatter agg -> coord head silu(.@cW1+cb1)@cW2 -> scatter dx
__global__ void __launch_bounds__(256, 1)
k_edge(const float* __restrict__ eW1, const float* __restrict__ eb1,
       const float* __restrict__ eW2, const float* __restrict__ eb2,
       const float* __restrict__ cW1, const float* __restrict__ cb1,
       const float* __restrict__ cW2,
       const int* __restrict__ edge_index,
       const float* __restrict__ edge_mask) {
    extern __shared__ float smem[];
    float* sW1  = smem;                 // 193*64
    float* sW2  = smem + 12352;         // 64*64
    float* sWc1 = smem + 16448;         // 64*64
    float* sWc2 = smem + 20544;         // 64
    float* sb1  = smem + 20608;
    float* sb2  = smem + 20672;
    float* sbc1 = smem + 20736;
    float* sA   = smem + 20800;         // 64 x SA_STRIDE
    float* sM   = smem + 33344;         // 64 x SM_STRIDE
    int*   sRow = (int*)(smem + 37696); // 64
    int*   sCol = (int*)(smem + 37760); // 64
    float* sRad = smem + 37824;         // 64
    float* sCD  = smem + 37888;         // 64*3
    float* sEM  = smem + 38080;         // 64
    float* sS   = smem + 38144;         // 64*16

    int tid = threadIdx.x;
    for (int i = tid; i < EK * 64; i += 256) sW1[i] = eW1[i];
    for (int i = tid; i < 64 * 64; i += 256) { sW2[i] = eW2[i]; sWc1[i] = cW1[i]; }
    if (tid < 64) { sWc2[tid] = cW2[tid]; sb1[tid] = eb1[tid]; sb2[tid] = eb2[tid]; sbc1[tid] = cb1[tid]; }

    int ebase = blockIdx.x * 64;
    if (tid < 64) {
        int e = ebase + tid;
        int r = edge_index[e];
        int c = edge_index[NE + e];
        sRow[tid] = r; sCol[tid] = c;
        float dx = g_x[r * 3 + 0] - g_x[c * 3 + 0];
        float dy = g_x[r * 3 + 1] - g_x[c * 3 + 1];
        float dz = g_x[r * 3 + 2] - g_x[c * 3 + 2];
        float rad = dx * dx + dy * dy + dz * dz;
        sRad[tid] = rad;
        float inv = 1.0f / (sqrtf(rad) + 1.0f);
        sCD[tid * 3 + 0] = dx * inv;
        sCD[tid * 3 + 1] = dy * inv;
        sCD[tid * 3 + 2] = dz * inv;
        sEM[tid] = edge_mask[e];
    }
    __syncthreads();

    // build A = [h[row] | h[col] | radial | e]  (64 x 193)
    for (int i = tid; i < 64 * EK; i += 256) {
        int el = i / EK;
        int k  = i - el * EK;
        float v;
        if (k < 64)        v = g_h[sRow[el] * 64 + k];
        else if (k < 128)  v = g_h[sCol[el] * 64 + (k - 64)];
        else if (k == 128) v = sRad[el];
        else               v = g_e[(size_t)(ebase + el) * 64 + (k - 129)];
        sA[el * SA_STRIDE + k] = v;
    }
    __syncthreads();

    int ty = tid >> 4, tx = tid & 15;
    int r0 = ty * 4, c0 = tx * 4;

    float acc[4][4];
#pragma unroll
    for (int i = 0; i < 4; i++)
#pragma unroll
        for (int j = 0; j < 4; j++) acc[i][j] = 0.0f;

    // GEMM1: K = 193
    for (int k = 0; k < EK; k++) {
        float4 wv = *(const float4*)(sW1 + k * 64 + c0);
        float w0 = wv.x, w1 = wv.y, w2 = wv.z, w3 = wv.w;
#pragma unroll
        for (int i = 0; i < 4; i++) {
            float a = sA[(r0 + i) * SA_STRIDE + k];
            acc[i][0] = fmaf(a, w0, acc[i][0]);
            acc[i][1] = fmaf(a, w1, acc[i][1]);
            acc[i][2] = fmaf(a, w2, acc[i][2]);
            acc[i][3] = fmaf(a, w3, acc[i][3]);
        }
    }
#pragma unroll
    for (int i = 0; i < 4; i++)
#pragma unroll
        for (int j = 0; j < 4; j++)
            sM[(r0 + i) * SM_STRIDE + c0 + j] = silu_f(acc[i][j] + sb1[c0 + j]);
    __syncthreads();

    // GEMM2: K = 64
#pragma unroll
    for (int i = 0; i < 4; i++)
#pragma unroll
        for (int j = 0; j < 4; j++) acc[i][j] = 0.0f;
    for (int k = 0; k < 64; k++) {
        float4 wv = *(const float4*)(sW2 + k * 64 + c0);
        float w0 = wv.x, w1 = wv.y, w2 = wv.z, w3 = wv.w;
#pragma unroll
        for (int i = 0; i < 4; i++) {
            float a = sM[(r0 + i) * SM_STRIDE + k];
            acc[i][0] = fmaf(a, w0, acc[i][0]);
            acc[i][1] = fmaf(a, w1, acc[i][1]);
            acc[i][2] = fmaf(a, w2, acc[i][2]);
            acc[i][3] = fmaf(a, w3, acc[i][3]);
        }
    }
    __syncthreads();  // all reads of sM (m1) complete

    float m[4][4];
#pragma unroll
    for (int i = 0; i < 4; i++) {
        float em = sEM[r0 + i];
#pragma unroll
        for (int j = 0; j < 4; j++)
            m[i][j] = silu_f(acc[i][j] + sb2[c0 + j]) * em;
    }
    // store e (updated edge feature), scatter agg, refill sM with m
#pragma unroll
    for (int i = 0; i < 4; i++) {
        float4 mv = make_float4(m[i][0], m[i][1], m[i][2], m[i][3]);
        *(float4*)(&g_e[(size_t)(ebase + r0 + i) * 64 + c0]) = mv;
        int rw = sRow[r0 + i];
#pragma unroll
        for (int j = 0; j < 4; j++) {
            sM[(r0 + i) * SM_STRIDE + c0 + j] = m[i][j];
            atomicAdd(&g_agg[rw * 64 + c0 + j], m[i][j]);
        }
    }
    __syncthreads();

    // GEMM3 (coord head): c1 = silu(m@cW1+cb1), s = c1 @ cW2
#pragma unroll
    for (int i = 0; i < 4; i++)
#pragma unroll
        for (int j = 0; j < 4; j++) acc[i][j] = 0.0f;
    for (int k = 0; k < 64; k++) {
        float4 wv = *(const float4*)(sWc1 + k * 64 + c0);
        float w0 = wv.x, w1 = wv.y, w2 = wv.z, w3 = wv.w;
#pragma unroll
        for (int i = 0; i < 4; i++) {
            float a = sM[(r0 + i) * SM_STRIDE + k];
            acc[i][0] = fmaf(a, w0, acc[i][0]);
            acc[i][1] = fmaf(a, w1, acc[i][1]);
            acc[i][2] = fmaf(a, w2, acc[i][2]);
            acc[i][3] = fmaf(a, w3, acc[i][3]);
        }
    }
#pragma unroll
    for (int i = 0; i < 4; i++) {
        float p = 0.0f;
#pragma unroll
        for (int j = 0; j < 4; j++)
            p += silu_f(acc[i][j] + sbc1[c0 + j]) * sWc2[c0 + j];
        sS[(r0 + i) * 16 + tx] = p;
    }
    __syncthreads();
    if (tid < 64) {
        float s = 0.0f;
#pragma unroll
        for (int u = 0; u < 16; u++) s += sS[tid * 16 + u];
        int r = sRow[tid];
        atomicAdd(&g_dx[r * 3 + 0], sCD[tid * 3 + 0] * s);
        atomicAdd(&g_dx[r * 3 + 1], sCD[tid * 3 + 1] * s);
        atomicAdd(&g_dx[r * 3 + 2], sCD[tid * 3 + 2] * s);
    }
}

// ---------------------------------------------------------------- node layer
__global__ void __launch_bounds__(256, 1)
k_node(const float* __restrict__ nW1, const float* __restrict__ nb1,
       const float* __restrict__ nW2, const float* __restrict__ nb2,
       const float* __restrict__ node_mask) {
    extern __shared__ float smem[];
    float* sW1 = smem;           // 128*64
    float* sW2 = smem + 8192;    // 64*64
    float* sb1 = smem + 12288;
    float* sb2 = smem + 12352;
    float* sA  = smem + 12416;   // 64 x 132
    float* sM  = smem + 20864;   // 64 x SM_STRIDE

    int tid = threadIdx.x;
    for (int i = tid; i < 128 * 64; i += 256) sW1[i] = nW1[i];
    for (int i = tid; i < 64 * 64; i += 256) sW2[i] = nW2[i];
    if (tid < 64) { sb1[tid] = nb1[tid]; sb2[tid] = nb2[tid]; }

    int nbase = blockIdx.x * 64;
    for (int i = tid; i < 64 * 128; i += 256) {
        int nl = i >> 7, k = i & 127;
        int node = nbase + nl;
        float v = 0.0f;
        if (node < NN) {
            if (k < 64) v = g_h[node * 64 + k];
            else { v = g_agg[node * 64 + (k - 64)]; g_agg[node * 64 + (k - 64)] = 0.0f; }
        }
        sA[nl * 132 + k] = v;
    }
    __syncthreads();

    int ty = tid >> 4, tx = tid & 15;
    int r0 = ty * 4, c0 = tx * 4;

    float acc[4][4];
#pragma unroll
    for (int i = 0; i < 4; i++)
#pragma unroll
        for (int j = 0; j < 4; j++) acc[i][j] = 0.0f;
    for (int k = 0; k < 128; k++) {
        float4 wv = *(const float4*)(sW1 + k * 64 + c0);
        float w0 = wv.x, w1 = wv.y, w2 = wv.z, w3 = wv.w;
#pragma unroll
        for (int i = 0; i < 4; i++) {
            float a = sA[(r0 + i) * 132 + k];
            acc[i][0] = fmaf(a, w0, acc[i][0]);
            acc[i][1] = fmaf(a, w1, acc[i][1]);
            acc[i][2] = fmaf(a, w2, acc[i][2]);
            acc[i][3] = fmaf(a, w3, acc[i][3]);
        }
    }
#pragma unroll
    for (int i = 0; i < 4; i++)
#pragma unroll
        for (int j = 0; j < 4; j++)
            sM[(r0 + i) * SM_STRIDE + c0 + j] = silu_f(acc[i][j] + sb1[c0 + j]);
    __syncthreads();

#pragma unroll
    for (int i = 0; i < 4; i++)
#pragma unroll
        for (int j = 0; j < 4; j++) acc[i][j] = 0.0f;
    for (int k = 0; k < 64; k++) {
        float4 wv = *(const float4*)(sW2 + k * 64 + c0);
        float w0 = wv.x, w1 = wv.y, w2 = wv.z, w3 = wv.w;
#pragma unroll
        for (int i = 0; i < 4; i++) {
            float a = sM[(r0 + i) * SM_STRIDE + k];
            acc[i][0] = fmaf(a, w0, acc[i][0]);
            acc[i][1] = fmaf(a, w1, acc[i][1]);
            acc[i][2] = fmaf(a, w2, acc[i][2]);
            acc[i][3] = fmaf(a, w3, acc[i][3]);
        }
    }
#pragma unroll
    for (int i = 0; i < 4; i++) {
        int node = nbase + r0 + i;
        if (node < NN) {
            float msk = node_mask[node];
#pragma unroll
            for (int j = 0; j < 4; j++) {
                int idx = node * 64 + c0 + j;
                g_h[idx] = (g_h[idx] + acc[i][j] + sb2[c0 + j]) * msk;
            }
        }
    }
}

__global__ void k_xupd(const float* __restrict__ node_mask) {
    int i = blockIdx.x * blockDim.x + threadIdx.x;
    if (i >= NN * 3) return;
    float v = (g_x[i] + g_dx[i]) * node_mask[i / 3];
    g_x[i] = v;
    g_dx[i] = 0.0f;
}

// ---------------------------------------------------------------- outputs
__global__ void k_out_h(const float* __restrict__ W, const float* __restrict__ b,
                        const float* __restrict__ node_mask, float* __restrict__ out) {
    __shared__ float sW[64 * 16];
    __shared__ float sb[16];
    int tid = threadIdx.x;
    for (int i = tid; i < 64 * 16; i += blockDim.x) sW[i] = W[i];
    if (tid < 16) sb[tid] = b[tid];
    __syncthreads();
    int gid = blockIdx.x * blockDim.x + tid;
    if (gid >= NN * 16) return;
    int n = gid >> 4, j = gid & 15;
    float acc = sb[j];
#pragma unroll
    for (int k = 0; k < 64; k++) acc += g_h[n * 64 + k] * sW[k * 16 + j];
    out[gid] = acc * node_mask[n];
}

__global__ void k_out_x(float* __restrict__ out) {
    int i = blockIdx.x * blockDim.x + threadIdx.x;
    if (i < NN * 3) out[i] = g_x[i];
}

__global__ void k_out_e(const float* __restrict__ W, const float* __restrict__ b,
                        const float* __restrict__ edge_mask, float* __restrict__ out) {
    __shared__ float sW[64 * 8];
    __shared__ float sb[8];
    int tid = threadIdx.x;
    for (int i = tid; i < 64 * 8; i += blockDim.x) sW[i] = W[i];
    if (tid < 8) sb[tid] = b[tid];
    __syncthreads();
    int gid = blockIdx.x * blockDim.x + tid;
    if (gid >= NE * 8) return;
    int e = gid >> 3, j = gid & 7;
    float acc = sb[j];
#pragma unroll
    for (int k = 0; k < 64; k++) acc += g_e[(size_t)e * 64 + k] * sW[k * 8 + j];
    out[gid] = acc * edge_mask[e];
}

// ---------------------------------------------------------------- launch
extern "C" void kernel_launch(void* const* d_in, const int* in_sizes, int n_in,
                              void* d_out, int out_size) {
    const float* h         = (const float*)d_in[0];
    const float* x         = (const float*)d_in[1];
    const float* edge_attr = (const float*)d_in[2];
    const float* node_mask = (const float*)d_in[3];
    const float* edge_mask = (const float*)d_in[4];
    const float* Wn_in  = (const float*)d_in[5];
    const float* bn_in  = (const float*)d_in[6];
    const float* Wn_out = (const float*)d_in[7];
    const float* bn_out = (const float*)d_in[8];
    const float* We_in  = (const float*)d_in[9];
    const float* be_in  = (const float*)d_in[10];
    const float* We_out = (const float*)d_in[11];
    const float* be_out = (const float*)d_in[12];
    const float* eW1 = (const float*)d_in[13];
    const float* eb1 = (const float*)d_in[14];
    const float* eW2 = (const float*)d_in[15];
    const float* eb2 = (const float*)d_in[16];
    const float* nW1 = (const float*)d_in[17];
    const float* nb1 = (const float*)d_in[18];
    const float* nW2 = (const float*)d_in[19];
    const float* nb2 = (const float*)d_in[20];
    const float* cW1 = (const float*)d_in[21];
    const float* cb1 = (const float*)d_in[22];
    const float* cW2 = (const float*)d_in[23];
    const int* edge_index = (const int*)d_in[24];
    float* out = (float*)d_out;

    cudaFuncSetAttribute(k_edge, cudaFuncAttributeMaxDynamicSharedMemorySize, EDGE_SMEM);
    cudaFuncSetAttribute(k_node, cudaFuncAttributeMaxDynamicSharedMemorySize, NODE_SMEM);

    k_node_embed<<<(NN * HD + 255) / 256, 256>>>(h, Wn_in, bn_in);
    k_edge_embed<<<(NE * HD + 255) / 256, 256>>>(edge_attr, We_in, be_in);
    k_xinit<<<(NN * 3 + 255) / 256, 256>>>(x);

    for (int l = 0; l < NLAYERS; l++) {
        k_edge<<<NE / 64, 256, EDGE_SMEM>>>(
            eW1 + (size_t)l * EK * 64, eb1 + l * 64,
            eW2 + (size_t)l * 64 * 64, eb2 + l * 64,
            cW1 + (size_t)l * 64 * 64, cb1 + l * 64,
            cW2 + (size_t)l * 64,
            edge_index, edge_mask);
        k_node<<<(NN + 63) / 64, 256, NODE_SMEM>>>(
            nW1 + (size_t)l * 128 * 64, nb1 + l * 64,
            nW2 + (size_t)l * 64 * 64, nb2 + l * 64,
            node_mask);
        k_xupd<<<(NN * 3 + 255) / 256, 256>>>(node_mask);
    }

    k_out_h<<<(NN * 16 + 255) / 256, 256>>>(Wn_out, bn_out, node_mask, out);
    k_out_x<<<(NN * 3 + 255) / 256, 256>>>(out + NN * 16);
    k_out_e<<<(NE * 8 + 255) / 256, 256>>>(We_out, be_out, edge_mask, out + NN * 16 + NN * 3);
}

// round 3
// speedup vs baseline: 1.5419x; 1.5419x over previous
#include <cuda_runtime.h>
#include <math.h>

#define NN 50000
#define NE 800000
#define HD 64
#define NLAYERS 4
#define EK 193          // 2H + 1 + H
#define SA_STRIDE 196
#define SM_STRIDE 68

// ---- edge kernel smem layout (floats), 128 edges / 1024 threads ----
#define EW1_OFF   0                    // 193*64 = 12352
#define EW2_OFF   12352                // 64*64  = 4096
#define EWC1_OFF  16448                // 64*64  = 4096
#define EWC2_OFF  20544                // 64
#define EB1_OFF   20608                // 64
#define EB2_OFF   20672                // 64
#define EBC1_OFF  20736                // 64
#define EROW_OFF  20800                // 128 (int)
#define ECOL_OFF  20928                // 128 (int)
#define ERAD_OFF  21056                // 128
#define EEM_OFF   21184                // 128
#define ECD_OFF   21312                // 128*3 = 384
#define EA_OFF    21696                // 128*196 = 25088  (overlaid by sM/sS later)
#define EDGE_SMEM_FLOATS (EA_OFF + 128 * SA_STRIDE)   // 46784 floats
#define EDGE_SMEM (EDGE_SMEM_FLOATS * 4)              // 187,136 B

#define NODE_SMEM (25216 * 4)

// persistent scratch (no runtime allocation allowed)
__device__ float g_h[NN * HD];
__device__ float g_e[NE * HD];
__device__ float g_x[NN * 3];
__device__ float g_dx[NN * 3];    // zero-initialized; restored to zero after use
__device__ float g_agg[NN * HD];  // zero-initialized; restored to zero after use

__device__ __forceinline__ float silu_f(float v) {
    return v / (1.0f + __expf(-v));
}

// ---------------------------------------------------------------- embeddings
__global__ void k_node_embed(const float* __restrict__ h,
                             const float* __restrict__ W,
                             const float* __restrict__ b) {
    __shared__ float sW[16 * 64];
    __shared__ float sb[64];
    int tid = threadIdx.x;
    for (int i = tid; i < 16 * 64; i += blockDim.x) sW[i] = W[i];
    if (tid < 64) sb[tid] = b[tid];
    __syncthreads();
    int gid = blockIdx.x * blockDim.x + tid;
    if (gid >= NN * HD) return;
    int n = gid >> 6, j = gid & 63;
    float acc = sb[j];
#pragma unroll
    for (int k = 0; k < 16; k++) acc += h[n * 16 + k] * sW[k * 64 + j];
    g_h[gid] = acc;
}

__global__ void k_edge_embed(const float* __restrict__ ea,
                             const float* __restrict__ W,
                             const float* __restrict__ b) {
    __shared__ float sW[8 * 64];
    __shared__ float sb[64];
    int tid = threadIdx.x;
    for (int i = tid; i < 8 * 64; i += blockDim.x) sW[i] = W[i];
    if (tid < 64) sb[tid] = b[tid];
    __syncthreads();
    int gid = blockIdx.x * blockDim.x + tid;
    if (gid >= NE * HD) return;
    int e = gid >> 6, j = gid & 63;
    float acc = sb[j];
#pragma unroll
    for (int k = 0; k < 8; k++) acc += ea[e * 8 + k] * sW[k * 64 + j];
    g_e[gid] = acc;
}

__global__ void k_xinit(const float* __restrict__ x) {
    int i = blockIdx.x * blockDim.x + threadIdx.x;
    if (i < NN * 3) g_x[i] = x[i];
}

// ---------------------------------------------------------------- edge layer
// One block = 128 edges, 1024 threads (32 warps). micro-tile 2x4 (64x16 thread grid).
__global__ void __launch_bounds__(1024, 1)
k_edge(const float* __restrict__ eW1, const float* __restrict__ eb1,
       const float* __restrict__ eW2, const float* __restrict__ eb2,
       const float* __restrict__ cW1, const float* __restrict__ cb1,
       const float* __restrict__ cW2,
       const int* __restrict__ edge_index,
       const float* __restrict__ edge_mask) {
    extern __shared__ float smem[];
    float* sW1  = smem + EW1_OFF;
    float* sW2  = smem + EW2_OFF;
    float* sWc1 = smem + EWC1_OFF;
    float* sWc2 = smem + EWC2_OFF;
    float* sb1  = smem + EB1_OFF;
    float* sb2  = smem + EB2_OFF;
    float* sbc1 = smem + EBC1_OFF;
    int*   sRow = (int*)(smem + EROW_OFF);
    int*   sCol = (int*)(smem + ECOL_OFF);
    float* sRad = smem + ERAD_OFF;
    float* sEM  = smem + EEM_OFF;
    float* sCD  = smem + ECD_OFF;
    float* sA   = smem + EA_OFF;          // 128 x SA_STRIDE
    float* sM   = smem + EA_OFF;          // overlay: 128 x SM_STRIDE (8704)
    float* sS   = smem + EA_OFF + 8704;   // overlay: 128 x 16

    int tid = threadIdx.x;
    for (int i = tid; i < EK * 64; i += 1024) sW1[i] = eW1[i];
    for (int i = tid; i < 64 * 64; i += 1024) { sW2[i] = eW2[i]; sWc1[i] = cW1[i]; }
    if (tid < 64) { sWc2[tid] = cW2[tid]; sb1[tid] = eb1[tid]; sb2[tid] = eb2[tid]; sbc1[tid] = cb1[tid]; }

    int ebase = blockIdx.x * 128;
    if (tid < 128) {
        int e = ebase + tid;
        int r = edge_index[e];
        int c = edge_index[NE + e];
        sRow[tid] = r; sCol[tid] = c;
        float dx = g_x[r * 3 + 0] - g_x[c * 3 + 0];
        float dy = g_x[r * 3 + 1] - g_x[c * 3 + 1];
        float dz = g_x[r * 3 + 2] - g_x[c * 3 + 2];
        float rad = dx * dx + dy * dy + dz * dz;
        sRad[tid] = rad;
        float inv = 1.0f / (sqrtf(rad) + 1.0f);
        sCD[tid * 3 + 0] = dx * inv;
        sCD[tid * 3 + 1] = dy * inv;
        sCD[tid * 3 + 2] = dz * inv;
        sEM[tid] = edge_mask[e];
    }
    __syncthreads();

    // build A = [h[row] | h[col] | radial | e]  (128 x 193)
    for (int i = tid; i < 128 * EK; i += 1024) {
        int el = i / EK;
        int k  = i - el * EK;
        float v;
        if (k < 64)        v = g_h[sRow[el] * 64 + k];
        else if (k < 128)  v = g_h[sCol[el] * 64 + (k - 64)];
        else if (k == 128) v = sRad[el];
        else               v = g_e[(size_t)(ebase + el) * 64 + (k - 129)];
        sA[el * SA_STRIDE + k] = v;
    }
    __syncthreads();

    int ty = tid >> 4, tx = tid & 15;  // ty 0..63, tx 0..15
    int r0 = ty * 2, c0 = tx * 4;

    float acc[2][4];
#pragma unroll
    for (int i = 0; i < 2; i++)
#pragma unroll
        for (int j = 0; j < 4; j++) acc[i][j] = 0.0f;

    // GEMM1: [128x193] @ [193x64]
#pragma unroll 4
    for (int k = 0; k < EK; k++) {
        float4 wv = *(const float4*)(sW1 + k * 64 + c0);
        float a0 = sA[(r0 + 0) * SA_STRIDE + k];
        float a1 = sA[(r0 + 1) * SA_STRIDE + k];
        acc[0][0] = fmaf(a0, wv.x, acc[0][0]); acc[0][1] = fmaf(a0, wv.y, acc[0][1]);
        acc[0][2] = fmaf(a0, wv.z, acc[0][2]); acc[0][3] = fmaf(a0, wv.w, acc[0][3]);
        acc[1][0] = fmaf(a1, wv.x, acc[1][0]); acc[1][1] = fmaf(a1, wv.y, acc[1][1]);
        acc[1][2] = fmaf(a1, wv.z, acc[1][2]); acc[1][3] = fmaf(a1, wv.w, acc[1][3]);
    }
    __syncthreads();   // all sA reads complete; sA region becomes free

    // write m1 = silu(acc + b1) into overlay sM
#pragma unroll
    for (int i = 0; i < 2; i++)
#pragma unroll
        for (int j = 0; j < 4; j++)
            sM[(r0 + i) * SM_STRIDE + c0 + j] = silu_f(acc[i][j] + sb1[c0 + j]);
    __syncthreads();

    // GEMM2: [128x64] @ [64x64]
#pragma unroll
    for (int i = 0; i < 2; i++)
#pragma unroll
        for (int j = 0; j < 4; j++) acc[i][j] = 0.0f;
#pragma unroll 4
    for (int k = 0; k < 64; k++) {
        float4 wv = *(const float4*)(sW2 + k * 64 + c0);
        float a0 = sM[(r0 + 0) * SM_STRIDE + k];
        float a1 = sM[(r0 + 1) * SM_STRIDE + k];
        acc[0][0] = fmaf(a0, wv.x, acc[0][0]); acc[0][1] = fmaf(a0, wv.y, acc[0][1]);
        acc[0][2] = fmaf(a0, wv.z, acc[0][2]); acc[0][3] = fmaf(a0, wv.w, acc[0][3]);
        acc[1][0] = fmaf(a1, wv.x, acc[1][0]); acc[1][1] = fmaf(a1, wv.y, acc[1][1]);
        acc[1][2] = fmaf(a1, wv.z, acc[1][2]); acc[1][3] = fmaf(a1, wv.w, acc[1][3]);
    }
    __syncthreads();   // all m1 reads complete

    float m[2][4];
#pragma unroll
    for (int i = 0; i < 2; i++) {
        float em = sEM[r0 + i];
#pragma unroll
        for (int j = 0; j < 4; j++)
            m[i][j] = silu_f(acc[i][j] + sb2[c0 + j]) * em;
    }
    // store e (updated edge feature), scatter agg, refill sM with m
#pragma unroll
    for (int i = 0; i < 2; i++) {
        float4 mv = make_float4(m[i][0], m[i][1], m[i][2], m[i][3]);
        *(float4*)(&g_e[(size_t)(ebase + r0 + i) * 64 + c0]) = mv;
        int rw = sRow[r0 + i];
#pragma unroll
        for (int j = 0; j < 4; j++) {
            sM[(r0 + i) * SM_STRIDE + c0 + j] = m[i][j];
            atomicAdd(&g_agg[rw * 64 + c0 + j], m[i][j]);
        }
    }
    __syncthreads();

    // GEMM3 (coord head): c1 = silu(m@cW1+cb1), s = c1 @ cW2
#pragma unroll
    for (int i = 0; i < 2; i++)
#pragma unroll
        for (int j = 0; j < 4; j++) acc[i][j] = 0.0f;
#pragma unroll 4
    for (int k = 0; k < 64; k++) {
        float4 wv = *(const float4*)(sWc1 + k * 64 + c0);
        float a0 = sM[(r0 + 0) * SM_STRIDE + k];
        float a1 = sM[(r0 + 1) * SM_STRIDE + k];
        acc[0][0] = fmaf(a0, wv.x, acc[0][0]); acc[0][1] = fmaf(a0, wv.y, acc[0][1]);
        acc[0][2] = fmaf(a0, wv.z, acc[0][2]); acc[0][3] = fmaf(a0, wv.w, acc[0][3]);
        acc[1][0] = fmaf(a1, wv.x, acc[1][0]); acc[1][1] = fmaf(a1, wv.y, acc[1][1]);
        acc[1][2] = fmaf(a1, wv.z, acc[1][2]); acc[1][3] = fmaf(a1, wv.w, acc[1][3]);
    }
    __syncthreads();   // all m reads complete; sS region free
#pragma unroll
    for (int i = 0; i < 2; i++) {
        float p = 0.0f;
#pragma unroll
        for (int j = 0; j < 4; j++)
            p += silu_f(acc[i][j] + sbc1[c0 + j]) * sWc2[c0 + j];
        sS[(r0 + i) * 16 + tx] = p;
    }
    __syncthreads();
    if (tid < 128) {
        float s = 0.0f;
#pragma unroll
        for (int u = 0; u < 16; u++) s += sS[tid * 16 + u];
        int r = sRow[tid];
        atomicAdd(&g_dx[r * 3 + 0], sCD[tid * 3 + 0] * s);
        atomicAdd(&g_dx[r * 3 + 1], sCD[tid * 3 + 1] * s);
        atomicAdd(&g_dx[r * 3 + 2], sCD[tid * 3 + 2] * s);
    }
}

// ---------------------------------------------------------------- node layer
__global__ void __launch_bounds__(256, 1)
k_node(const float* __restrict__ nW1, const float* __restrict__ nb1,
       const float* __restrict__ nW2, const float* __restrict__ nb2,
       const float* __restrict__ node_mask) {
    extern __shared__ float smem[];
    float* sW1 = smem;           // 128*64
    float* sW2 = smem + 8192;    // 64*64
    float* sb1 = smem + 12288;
    float* sb2 = smem + 12352;
    float* sA  = smem + 12416;   // 64 x 132
    float* sM  = smem + 20864;   // 64 x SM_STRIDE

    int tid = threadIdx.x;
    for (int i = tid; i < 128 * 64; i += 256) sW1[i] = nW1[i];
    for (int i = tid; i < 64 * 64; i += 256) sW2[i] = nW2[i];
    if (tid < 64) { sb1[tid] = nb1[tid]; sb2[tid] = nb2[tid]; }

    int nbase = blockIdx.x * 64;
    for (int i = tid; i < 64 * 128; i += 256) {
        int nl = i >> 7, k = i & 127;
        int node = nbase + nl;
        float v = 0.0f;
        if (node < NN) {
            if (k < 64) v = g_h[node * 64 + k];
            else { v = g_agg[node * 64 + (k - 64)]; g_agg[node * 64 + (k - 64)] = 0.0f; }
        }
        sA[nl * 132 + k] = v;
    }
    __syncthreads();

    int ty = tid >> 4, tx = tid & 15;
    int r0 = ty * 4, c0 = tx * 4;

    float acc[4][4];
#pragma unroll
    for (int i = 0; i < 4; i++)
#pragma unroll
        for (int j = 0; j < 4; j++) acc[i][j] = 0.0f;
#pragma unroll 4
    for (int k = 0; k < 128; k++) {
        float4 wv = *(const float4*)(sW1 + k * 64 + c0);
        float w0 = wv.x, w1 = wv.y, w2 = wv.z, w3 = wv.w;
#pragma unroll
        for (int i = 0; i < 4; i++) {
            float a = sA[(r0 + i) * 132 + k];
            acc[i][0] = fmaf(a, w0, acc[i][0]);
            acc[i][1] = fmaf(a, w1, acc[i][1]);
            acc[i][2] = fmaf(a, w2, acc[i][2]);
            acc[i][3] = fmaf(a, w3, acc[i][3]);
        }
    }
#pragma unroll
    for (int i = 0; i < 4; i++)
#pragma unroll
        for (int j = 0; j < 4; j++)
            sM[(r0 + i) * SM_STRIDE + c0 + j] = silu_f(acc[i][j] + sb1[c0 + j]);
    __syncthreads();

#pragma unroll
    for (int i = 0; i < 4; i++)
#pragma unroll
        for (int j = 0; j < 4; j++) acc[i][j] = 0.0f;
#pragma unroll 4
    for (int k = 0; k < 64; k++) {
        float4 wv = *(const float4*)(sW2 + k * 64 + c0);
        float w0 = wv.x, w1 = wv.y, w2 = wv.z, w3 = wv.w;
#pragma unroll
        for (int i = 0; i < 4; i++) {
            float a = sM[(r0 + i) * SM_STRIDE + k];
            acc[i][0] = fmaf(a, w0, acc[i][0]);
            acc[i][1] = fmaf(a, w1, acc[i][1]);
            acc[i][2] = fmaf(a, w2, acc[i][2]);
            acc[i][3] = fmaf(a, w3, acc[i][3]);
        }
    }
#pragma unroll
    for (int i = 0; i < 4; i++) {
        int node = nbase + r0 + i;
        if (node < NN) {
            float msk = node_mask[node];
#pragma unroll
            for (int j = 0; j < 4; j++) {
                int idx = node * 64 + c0 + j;
                g_h[idx] = (g_h[idx] + acc[i][j] + sb2[c0 + j]) * msk;
            }
        }
    }
}

__global__ void k_xupd(const float* __restrict__ node_mask) {
    int i = blockIdx.x * blockDim.x + threadIdx.x;
    if (i >= NN * 3) return;
    float v = (g_x[i] + g_dx[i]) * node_mask[i / 3];
    g_x[i] = v;
    g_dx[i] = 0.0f;
}

// ---------------------------------------------------------------- outputs
__global__ void k_out_h(const float* __restrict__ W, const float* __restrict__ b,
                        const float* __restrict__ node_mask, float* __restrict__ out) {
    __shared__ float sW[64 * 16];
    __shared__ float sb[16];
    int tid = threadIdx.x;
    for (int i = tid; i < 64 * 16; i += blockDim.x) sW[i] = W[i];
    if (tid < 16) sb[tid] = b[tid];
    __syncthreads();
    int gid = blockIdx.x * blockDim.x + tid;
    if (gid >= NN * 16) return;
    int n = gid >> 4, j = gid & 15;
    float acc = sb[j];
#pragma unroll
    for (int k = 0; k < 64; k++) acc += g_h[n * 64 + k] * sW[k * 16 + j];
    out[gid] = acc * node_mask[n];
}

__global__ void k_out_x(float* __restrict__ out) {
    int i = blockIdx.x * blockDim.x + threadIdx.x;
    if (i < NN * 3) out[i] = g_x[i];
}

__global__ void k_out_e(const float* __restrict__ W, const float* __restrict__ b,
                        const float* __restrict__ edge_mask, float* __restrict__ out) {
    __shared__ float sW[64 * 8];
    __shared__ float sb[8];
    int tid = threadIdx.x;
    for (int i = tid; i < 64 * 8; i += blockDim.x) sW[i] = W[i];
    if (tid < 8) sb[tid] = b[tid];
    __syncthreads();
    int gid = blockIdx.x * blockDim.x + tid;
    if (gid >= NE * 8) return;
    int e = gid >> 3, j = gid & 7;
    float acc = sb[j];
#pragma unroll
    for (int k = 0; k < 64; k++) acc += g_e[(size_t)e * 64 + k] * sW[k * 8 + j];
    out[gid] = acc * edge_mask[e];
}

// ---------------------------------------------------------------- launch
extern "C" void kernel_launch(void* const* d_in, const int* in_sizes, int n_in,
                              void* d_out, int out_size) {
    const float* h         = (const float*)d_in[0];
    const float* x         = (const float*)d_in[1];
    const float* edge_attr = (const float*)d_in[2];
    const float* node_mask = (const float*)d_in[3];
    const float* edge_mask = (const float*)d_in[4];
    const float* Wn_in  = (const float*)d_in[5];
    const float* bn_in  = (const float*)d_in[6];
    const float* Wn_out = (const float*)d_in[7];
    const float* bn_out = (const float*)d_in[8];
    const float* We_in  = (const float*)d_in[9];
    const float* be_in  = (const float*)d_in[10];
    const float* We_out = (const float*)d_in[11];
    const float* be_out = (const float*)d_in[12];
    const float* eW1 = (const float*)d_in[13];
    const float* eb1 = (const float*)d_in[14];
    const float* eW2 = (const float*)d_in[15];
    const float* eb2 = (const float*)d_in[16];
    const float* nW1 = (const float*)d_in[17];
    const float* nb1 = (const float*)d_in[18];
    const float* nW2 = (const float*)d_in[19];
    const float* nb2 = (const float*)d_in[20];
    const float* cW1 = (const float*)d_in[21];
    const float* cb1 = (const float*)d_in[22];
    const float* cW2 = (const float*)d_in[23];
    const int* edge_index = (const int*)d_in[24];
    float* out = (float*)d_out;

    cudaFuncSetAttribute(k_edge, cudaFuncAttributeMaxDynamicSharedMemorySize, EDGE_SMEM);
    cudaFuncSetAttribute(k_node, cudaFuncAttributeMaxDynamicSharedMemorySize, NODE_SMEM);

    k_node_embed<<<(NN * HD + 255) / 256, 256>>>(h, Wn_in, bn_in);
    k_edge_embed<<<(NE * HD + 255) / 256, 256>>>(edge_attr, We_in, be_in);
    k_xinit<<<(NN * 3 + 255) / 256, 256>>>(x);

    for (int l = 0; l < NLAYERS; l++) {
        k_edge<<<NE / 128, 1024, EDGE_SMEM>>>(
            eW1 + (size_t)l * EK * 64, eb1 + l * 64,
            eW2 + (size_t)l * 64 * 64, eb2 + l * 64,
            cW1 + (size_t)l * 64 * 64, cb1 + l * 64,
            cW2 + (size_t)l * 64,
            edge_index, edge_mask);
        k_node<<<(NN + 63) / 64, 256, NODE_SMEM>>>(
            nW1 + (size_t)l * 128 * 64, nb1 + l * 64,
            nW2 + (size_t)l * 64 * 64, nb2 + l * 64,
            node_mask);
        k_xupd<<<(NN * 3 + 255) / 256, 256>>>(node_mask);
    }

    k_out_h<<<(NN * 16 + 255) / 256, 256>>>(Wn_out, bn_out, node_mask, out);
    k_out_x<<<(NN * 3 + 255) / 256, 256>>>(out + NN * 16);
    k_out_e<<<(NE * 8 + 255) / 256, 256>>>(We_out, be_out, edge_mask, out + NN * 16 + NN * 3);
}